// round 9
// baseline (speedup 1.0000x reference)
#include <cuda_runtime.h>
#include <cuda_fp16.h>
#include <cuda_bf16.h>
#include <cstdint>

#define NN    8192
#define INF   512
#define OUTF  256
#define MAXNB 1024

// ---------------- scratch (__device__ globals: allocation-free rule) --------
__device__ float          g_fsp[2][NN];     // f_src partials (bn 0/1)
__device__ float          g_fdp[2][NN];
__device__ __half         g_pack[NN * 512]; // [row][0..255]=h, [256..511]=hgc
__device__ __nv_bfloat16  g_xh[NN * INF];   // bf16 hi of X  [row][512]
__device__ __nv_bfloat16  g_xl[NN * INF];   // bf16 lo of X
__device__ __nv_bfloat16  g_bh[INF * 512];  // [k][512] = W | Wgc (hi)
__device__ __nv_bfloat16  g_bl[INF * 512];  // lo

// ---------------- helpers ---------------------------------------------------
__device__ __forceinline__ uint32_t smem_u32(const void* p) {
    uint32_t a;
    asm("{ .reg .u64 t; cvta.to.shared.u64 t, %1; cvt.u32.u64 %0, t; }"
        : "=r"(a) : "l"(p));
    return a;
}
#define CPASYNC16(dst, src) \
    asm volatile("cp.async.cg.shared.global [%0], [%1], 16;" \
                 :: "r"(dst), "l"(src) : "memory")
#define CPCOMMIT() asm volatile("cp.async.commit_group;" ::: "memory")
#define CPWAIT(n)  asm volatile("cp.async.wait_group %0;" :: "n"(n) : "memory")

__device__ __forceinline__ void ldsm_x4(uint32_t (&r)[4], uint32_t addr) {
    asm volatile("ldmatrix.sync.aligned.m8n8.x4.shared.b16 {%0,%1,%2,%3}, [%4];"
                 : "=r"(r[0]), "=r"(r[1]), "=r"(r[2]), "=r"(r[3]) : "r"(addr));
}
__device__ __forceinline__ void ldsm_x4t(uint32_t (&r)[4], uint32_t addr) {
    asm volatile("ldmatrix.sync.aligned.m8n8.x4.trans.shared.b16 {%0,%1,%2,%3}, [%4];"
                 : "=r"(r[0]), "=r"(r[1]), "=r"(r[2]), "=r"(r[3]) : "r"(addr));
}
__device__ __forceinline__ void mma_bf16(float* c, const uint32_t* a,
                                         uint32_t b0, uint32_t b1) {
    asm volatile("mma.sync.aligned.m16n8k16.row.col.f32.bf16.bf16.f32 "
                 "{%0,%1,%2,%3}, {%4,%5,%6,%7}, {%8,%9}, {%0,%1,%2,%3};"
                 : "+f"(c[0]), "+f"(c[1]), "+f"(c[2]), "+f"(c[3])
                 : "r"(a[0]), "r"(a[1]), "r"(a[2]), "r"(a[3]), "r"(b0), "r"(b1));
}

// ---------------------------------------------------------------------------
// prepX: X fp32 -> (Xh, Xl) bf16 split
// ---------------------------------------------------------------------------
__global__ __launch_bounds__(256) void prepX(const float* __restrict__ X) {
    int i = blockIdx.x * 256 + threadIdx.x;          // float4 index
    float4 v = ((const float4*)X)[i];
    __nv_bfloat16 hv[4], lv[4];
    float f[4] = {v.x, v.y, v.z, v.w};
    #pragma unroll
    for (int j = 0; j < 4; j++) {
        hv[j] = __float2bfloat16_rn(f[j]);
        lv[j] = __float2bfloat16_rn(f[j] - __bfloat162float(hv[j]));
    }
    *(uint2*)(g_xh + (size_t)i * 4) = *(uint2*)hv;
    *(uint2*)(g_xl + (size_t)i * 4) = *(uint2*)lv;
}

// ---------------------------------------------------------------------------
// prepB: W,Wgc [512][256] fp32 -> g_bh/g_bl [512][512] bf16 (no transpose)
// ---------------------------------------------------------------------------
__global__ __launch_bounds__(256) void prepB(const float* __restrict__ W,
                                             const float* __restrict__ Wgc) {
    int k = blockIdx.x, n = threadIdx.x;
    float w = W[k * 256 + n];
    __nv_bfloat16 hb = __float2bfloat16_rn(w);
    g_bh[k * 512 + n] = hb;
    g_bl[k * 512 + n] = __float2bfloat16_rn(w - __bfloat162float(hb));
    float wg = Wgc[k * 256 + n];
    hb = __float2bfloat16_rn(wg);
    g_bh[k * 512 + 256 + n] = hb;
    g_bl[k * 512 + 256 + n] = __float2bfloat16_rn(wg - __bfloat162float(hb));
}

// ---------------------------------------------------------------------------
// kernelGEMM: C[8192 x 512] = Xsplit @ Bsplit (3-term bf16), K'=1536.
// Block tile 64m x 128n, grid (128, 4). 48 chunks of K=32, cp.async dbuf.
// Epilogue: fp16 pack + in-block reduced f_src/f_dst partials (per bn half).
// ---------------------------------------------------------------------------
#define ABYTES 5120
#define BUFB   13824
__global__ __launch_bounds__(256, 2) void kernelGEMM(const float* __restrict__ avec) {
    __shared__ __align__(16) char sm_ab[2 * BUFB];
    __shared__ float s_avec[512];
    __shared__ float s_fs[4][64], s_fd[4][64];

    const int bm = blockIdx.x, bn = blockIdx.y;      // bn: 0,1=h  2,3=hgc
    const int m0 = bm * 64;
    const int tid = threadIdx.x;
    const int wid = tid >> 5, lane = tid & 31;
    const int wm = wid & 1, wn = wid >> 1;           // warp tile 32m x 32n
    const uint32_t smbase = smem_u32(sm_ab);

    s_avec[tid] = avec[tid];
    s_avec[tid + 256] = avec[tid + 256];

    float cacc[2][4][4];
    #pragma unroll
    for (int i = 0; i < 2; i++)
        #pragma unroll
        for (int j = 0; j < 4; j++)
            #pragma unroll
            for (int e = 0; e < 4; e++) cacc[i][j][e] = 0.f;

    auto issue = [&](int c) {
        uint32_t buf = smbase + (uint32_t)(c & 1) * BUFB;
        int seg = c >> 4;
        const uint4* asrc = (const uint4*)((seg < 2) ? g_xh : g_xl);
        const uint4* bsrc = (const uint4*)((seg == 1) ? g_bl : g_bh);
        int kq = (c & 15) * 4;
        {   // A: 64 rows x 4 uint4 = 256 loads, 1/thread
            int r = tid >> 2, q = tid & 3;
            CPASYNC16(buf + r * 80 + q * 16, asrc + (size_t)(m0 + r) * 64 + kq + q);
        }
        int kr0 = (c & 15) * 32;
        #pragma unroll
        for (int i = 0; i < 2; i++) {                // B: 32 rows x 16 uint4
            int idx = tid + 256 * i;
            int rr = idx >> 4, q = idx & 15;
            CPASYNC16(buf + ABYTES + rr * 272 + q * 16,
                      bsrc + (size_t)(kr0 + rr) * 64 + bn * 16 + q);
        }
    };

    issue(0); CPCOMMIT();
    for (int c = 0; c < 48; c++) {
        if (c + 1 < 48) { issue(c + 1); CPCOMMIT(); CPWAIT(1); }
        else            { CPWAIT(0); }
        __syncthreads();
        uint32_t Ab = smbase + (uint32_t)(c & 1) * BUFB;
        uint32_t Bb = Ab + ABYTES;
        #pragma unroll
        for (int ks = 0; ks < 2; ks++) {
            int kk = ks * 16;
            uint32_t a[2][4], b[2][4];
            #pragma unroll
            for (int mf = 0; mf < 2; mf++)
                ldsm_x4(a[mf], Ab + (uint32_t)((wm * 32 + mf * 16 + (lane & 15)) * 80
                                               + (kk + (lane >> 4) * 8) * 2));
            #pragma unroll
            for (int ng = 0; ng < 2; ng++)
                ldsm_x4t(b[ng], Bb + (uint32_t)((kk + (lane & 15)) * 272
                                                + (wn * 32 + ng * 16 + (lane >> 4) * 8) * 2));
            #pragma unroll
            for (int mf = 0; mf < 2; mf++)
                #pragma unroll
                for (int nf = 0; nf < 4; nf++)
                    mma_bf16(cacc[mf][nf], a[mf],
                             b[nf >> 1][(nf & 1) * 2], b[nf >> 1][(nf & 1) * 2 + 1]);
        }
        __syncthreads();
    }

    // -------- epilogue: fp16 pack + staged f partials --------
    #pragma unroll
    for (int mf = 0; mf < 2; mf++) {
        #pragma unroll
        for (int half = 0; half < 2; half++) {
            int rl = wm * 32 + mf * 16 + (lane >> 2) + half * 8;   // local row
            int colbase = bn * 128 + wn * 32 + 2 * (lane & 3);
            __half2* dst = (__half2*)g_pack + ((size_t)(m0 + rl) * 512 + colbase) / 2;
            float s1 = 0.f, s2 = 0.f;
            #pragma unroll
            for (int nf = 0; nf < 4; nf++) {
                float v0 = cacc[mf][nf][half * 2 + 0];
                float v1 = cacc[mf][nf][half * 2 + 1];
                if (bn < 2) {
                    int cc = colbase + nf * 8;
                    s1 += v0 * s_avec[cc] + v1 * s_avec[cc + 1];
                    s2 += v0 * s_avec[256 + cc] + v1 * s_avec[256 + cc + 1];
                }
                dst[nf * 4] = __floats2half2_rn(v0, v1);
            }
            if (bn < 2) {
                s1 += __shfl_xor_sync(0xFFFFFFFFu, s1, 1);
                s1 += __shfl_xor_sync(0xFFFFFFFFu, s1, 2);
                s2 += __shfl_xor_sync(0xFFFFFFFFu, s2, 1);
                s2 += __shfl_xor_sync(0xFFFFFFFFu, s2, 2);
                if ((lane & 3) == 0) {
                    s_fs[wn][rl] = s1;
                    s_fd[wn][rl] = s2;
                }
            }
        }
    }
    if (bn < 2) {
        __syncthreads();
        if (tid < 64) {
            g_fsp[bn][m0 + tid] = s_fs[0][tid] + s_fs[1][tid] +
                                  s_fs[2][tid] + s_fs[3][tid];
            g_fdp[bn][m0 + tid] = s_fd[0][tid] + s_fd[1][tid] +
                                  s_fd[2][tid] + s_fd[3][tid];
        }
    }
}

// ---------------------------------------------------------------------------
// kernelB: fused adjacency scan + masked softmax + gather (att*h + hgc).
// One block per row. Scan (DRAM) overlaps gather (L2) across blocks.
// Gather: warp w handles neighbor subset k%8==w, 32 lanes x 8 cols (uint4).
// ---------------------------------------------------------------------------
__global__ __launch_bounds__(256) void kernelB(const float* __restrict__ adj,
                                               const float* __restrict__ bgc,
                                               float* __restrict__ out) {
    __shared__ int   s_idx[MAXNB];
    __shared__ float s_e[MAXNB];
    __shared__ float s_red[256];
    __shared__ float s_att[8 * 256];
    __shared__ float s_gc[8 * 256];
    __shared__ int   s_cnt;

    const int row = blockIdx.x;
    const int tid = threadIdx.x;
    const int lane = tid & 31;
    const int wrp = tid >> 5;

    if (tid == 0) s_cnt = 0;
    __syncthreads();

    // -------- phase 1: scan adj row with ballot compaction --------
    const float4* arow = (const float4*)(adj + (size_t)row * NN);
    #pragma unroll
    for (int r = 0; r < 8; r++) {
        int q = tid + 256 * r;
        float4 v = arow[q];
        float comp[4] = {v.x, v.y, v.z, v.w};
        #pragma unroll
        for (int cidx = 0; cidx < 4; cidx++) {
            bool hit = comp[cidx] > 0.f;
            unsigned m = __ballot_sync(0xFFFFFFFFu, hit);
            if (m) {
                int base;
                if (lane == 0) base = atomicAdd(&s_cnt, __popc(m));
                base = __shfl_sync(0xFFFFFFFFu, base, 0);
                if (hit) {
                    int pos = base + __popc(m & ((1u << lane) - 1u));
                    if (pos < MAXNB)
                        s_idx[pos] = (q * 4 + cidx) * 512;
                }
            }
        }
    }
    __syncthreads();
    const int cnt = min(s_cnt, MAXNB);

    if (cnt > 0) {
        // -------- phase 2: logits + softmax --------
        const float fsi = g_fsp[0][row] + g_fsp[1][row];
        float lm = -3e38f;
        for (int k = tid; k < cnt; k += 256) {
            int j = s_idx[k] >> 9;
            float e = fsi + g_fdp[0][j] + g_fdp[1][j];
            e = (e > 0.f) ? e : 0.2f * e;
            s_e[k] = e;
            lm = fmaxf(lm, e);
        }
        s_red[tid] = lm;
        __syncthreads();
        #pragma unroll
        for (int o = 128; o; o >>= 1) {
            if (tid < o) s_red[tid] = fmaxf(s_red[tid], s_red[tid + o]);
            __syncthreads();
        }
        const float mx = s_red[0];
        __syncthreads();

        float ls = 0.f;
        for (int k = tid; k < cnt; k += 256) {
            float w = expf(s_e[k] - mx);
            s_e[k] = w;
            ls += w;
        }
        s_red[tid] = ls;
        __syncthreads();
        #pragma unroll
        for (int o = 128; o; o >>= 1) {
            if (tid < o) s_red[tid] += s_red[tid + o];
            __syncthreads();
        }
        const float inv = 1.0f / s_red[0];
        __syncthreads();

        // -------- phase 3: gather; warp = neighbor subset, lane = 8-col group
        float aa[8], gg[8];
        #pragma unroll
        for (int u = 0; u < 8; u++) { aa[u] = 0.f; gg[u] = 0.f; }
        const __half* hp = (const __half*)g_pack;
        #pragma unroll 4
        for (int k = wrp; k < cnt; k += 8) {
            int joff = s_idx[k];
            float w = s_e[k];
            uint4 hv = *(const uint4*)(hp + joff + 8 * lane);
            uint4 gv = *(const uint4*)(hp + joff + 256 + 8 * lane);
            const __half2* h2 = (const __half2*)&hv;
            const __half2* g2 = (const __half2*)&gv;
            #pragma unroll
            for (int p = 0; p < 4; p++) {
                float2 hf = __half22float2(h2[p]);
                float2 gf = __half22float2(g2[p]);
                aa[2 * p]     += w * hf.x;
                aa[2 * p + 1] += w * hf.y;
                gg[2 * p]     += gf.x;
                gg[2 * p + 1] += gf.y;
            }
        }
        #pragma unroll
        for (int p = 0; p < 2; p++) {
            *(float4*)(s_att + wrp * 256 + lane * 8 + p * 4) =
                make_float4(aa[p * 4], aa[p * 4 + 1], aa[p * 4 + 2], aa[p * 4 + 3]);
            *(float4*)(s_gc + wrp * 256 + lane * 8 + p * 4) =
                make_float4(gg[p * 4], gg[p * 4 + 1], gg[p * 4 + 2], gg[p * 4 + 3]);
        }
        __syncthreads();

        float sa = 0.f, sg = 0.f;
        #pragma unroll
        for (int w = 0; w < 8; w++) {
            sa += s_att[w * 256 + tid];
            sg += s_gc[w * 256 + tid];
        }
        out[(size_t)row * OUTF + tid] = bgc[tid] + inv * sa + sg;
    } else {
        // all-masked row: softmax uniform 1/N over all cols; gc = bias only
        const __half* hp = (const __half*)g_pack;
        float acc = 0.f;
        for (int j = 0; j < NN; j++)
            acc += __half2float(hp[(size_t)j * 512 + tid]);
        out[(size_t)row * OUTF + tid] = bgc[tid] + acc * (1.0f / (float)NN);
    }
}

// ---------------------------------------------------------------------------
extern "C" void kernel_launch(void* const* d_in, const int* in_sizes, int n_in,
                              void* d_out, int out_size) {
    const float* X   = (const float*)d_in[0];  // [8192, 512]
    const float* adj = (const float*)d_in[1];  // [8192, 8192]
    const float* W   = (const float*)d_in[2];  // [512, 256]
    const float* a   = (const float*)d_in[3];  // [512, 1]
    const float* Wgc = (const float*)d_in[4];  // [512, 256]
    const float* bgc = (const float*)d_in[5];  // [256]
    float* out = (float*)d_out;                // [8192, 256]

    prepX<<<NN * INF / 4 / 256, 256>>>(X);
    prepB<<<512, 256>>>(W, Wgc);
    kernelGEMM<<<dim3(128, 4), 256>>>(a);
    kernelB<<<NN, 256>>>(adj, bgc, out);
}

// round 12
// speedup vs baseline: 1.1247x; 1.1247x over previous
#include <cuda_runtime.h>
#include <cuda_fp16.h>
#include <cuda_bf16.h>
#include <cstdint>

#define NN    8192
#define INF   512
#define OUTF  256
#define MAXNB 1024

// ---------------- scratch (__device__ globals: allocation-free rule) --------
__device__ float          g_fsp[2][NN];     // f_src partials (bn 0/1)
__device__ float          g_fdp[2][NN];
__device__ __half         g_pack[NN * 512]; // [row][0..255]=h, [256..511]=hgc
__device__ int            g_ncnt[NN];
__device__ int            g_nidx[NN * MAXNB]; // pre-scaled j*512
__device__ __nv_bfloat16  g_xh[NN * INF];   // bf16 hi of X  [row][512]
__device__ __nv_bfloat16  g_xl[NN * INF];   // bf16 lo of X
__device__ __nv_bfloat16  g_bh[INF * 512];  // [k][512] = W | Wgc (hi)
__device__ __nv_bfloat16  g_bl[INF * 512];  // lo

// ---------------- helpers ---------------------------------------------------
__device__ __forceinline__ uint32_t smem_u32(const void* p) {
    uint32_t a;
    asm("{ .reg .u64 t; cvta.to.shared.u64 t, %1; cvt.u32.u64 %0, t; }"
        : "=r"(a) : "l"(p));
    return a;
}
#define CPASYNC16(dst, src) \
    asm volatile("cp.async.cg.shared.global [%0], [%1], 16;" \
                 :: "r"(dst), "l"(src) : "memory")
#define CPCOMMIT() asm volatile("cp.async.commit_group;" ::: "memory")
#define CPWAIT(n)  asm volatile("cp.async.wait_group %0;" :: "n"(n) : "memory")

__device__ __forceinline__ void ldsm_x4(uint32_t (&r)[4], uint32_t addr) {
    asm volatile("ldmatrix.sync.aligned.m8n8.x4.shared.b16 {%0,%1,%2,%3}, [%4];"
                 : "=r"(r[0]), "=r"(r[1]), "=r"(r[2]), "=r"(r[3]) : "r"(addr));
}
__device__ __forceinline__ void ldsm_x4t(uint32_t (&r)[4], uint32_t addr) {
    asm volatile("ldmatrix.sync.aligned.m8n8.x4.trans.shared.b16 {%0,%1,%2,%3}, [%4];"
                 : "=r"(r[0]), "=r"(r[1]), "=r"(r[2]), "=r"(r[3]) : "r"(addr));
}
__device__ __forceinline__ void mma_bf16(float* c, const uint32_t* a,
                                         uint32_t b0, uint32_t b1) {
    asm volatile("mma.sync.aligned.m16n8k16.row.col.f32.bf16.bf16.f32 "
                 "{%0,%1,%2,%3}, {%4,%5,%6,%7}, {%8,%9}, {%0,%1,%2,%3};"
                 : "+f"(c[0]), "+f"(c[1]), "+f"(c[2]), "+f"(c[3])
                 : "r"(a[0]), "r"(a[1]), "r"(a[2]), "r"(a[3]), "r"(b0), "r"(b1));
}

// ---------------------------------------------------------------------------
// prepX: X fp32 -> (Xh, Xl) bf16 split
// ---------------------------------------------------------------------------
__global__ __launch_bounds__(256) void prepX(const float* __restrict__ X) {
    int i = blockIdx.x * 256 + threadIdx.x;          // float4 index
    float4 v = ((const float4*)X)[i];
    __nv_bfloat16 hv[4], lv[4];
    float f[4] = {v.x, v.y, v.z, v.w};
    #pragma unroll
    for (int j = 0; j < 4; j++) {
        hv[j] = __float2bfloat16_rn(f[j]);
        lv[j] = __float2bfloat16_rn(f[j] - __bfloat162float(hv[j]));
    }
    *(uint2*)(g_xh + (size_t)i * 4) = *(uint2*)hv;
    *(uint2*)(g_xl + (size_t)i * 4) = *(uint2*)lv;
}

// ---------------------------------------------------------------------------
// prepB: W,Wgc [512][256] fp32 -> g_bh/g_bl [512][512] bf16 (no transpose)
// ---------------------------------------------------------------------------
__global__ __launch_bounds__(256) void prepB(const float* __restrict__ W,
                                             const float* __restrict__ Wgc) {
    int k = blockIdx.x, n = threadIdx.x;
    float w = W[k * 256 + n];
    __nv_bfloat16 hb = __float2bfloat16_rn(w);
    g_bh[k * 512 + n] = hb;
    g_bl[k * 512 + n] = __float2bfloat16_rn(w - __bfloat162float(hb));
    float wg = Wgc[k * 256 + n];
    hb = __float2bfloat16_rn(wg);
    g_bh[k * 512 + 256 + n] = hb;
    g_bl[k * 512 + 256 + n] = __float2bfloat16_rn(wg - __bfloat162float(hb));
}

// ---------------------------------------------------------------------------
// kernelScan: pure-streaming adjacency scan. One block per row; front-batched
// loads (MLP=8); ballot compaction -> g_nidx/g_ncnt. Minimal regs/smem so it
// runs at full occupancy and saturates HBM.
// ---------------------------------------------------------------------------
__global__ __launch_bounds__(256) void kernelScan(const float* __restrict__ adj) {
    __shared__ int s_cnt;
    const int row = blockIdx.x;
    const int tid = threadIdx.x;
    const int lane = tid & 31;
    if (tid == 0) s_cnt = 0;
    __syncthreads();

    const float4* arow = (const float4*)(adj + (size_t)row * NN);
    float4 v[8];
    #pragma unroll
    for (int r = 0; r < 8; r++) v[r] = arow[tid + 256 * r];

    int* dst = g_nidx + row * MAXNB;
    #pragma unroll
    for (int r = 0; r < 8; r++) {
        int q = tid + 256 * r;
        float comp[4] = {v[r].x, v[r].y, v[r].z, v[r].w};
        #pragma unroll
        for (int ci = 0; ci < 4; ci++) {
            bool hit = comp[ci] > 0.f;
            unsigned m = __ballot_sync(0xFFFFFFFFu, hit);
            if (m) {
                int base;
                if (lane == 0) base = atomicAdd(&s_cnt, __popc(m));
                base = __shfl_sync(0xFFFFFFFFu, base, 0);
                if (hit) {
                    int pos = base + __popc(m & ((1u << lane) - 1u));
                    if (pos < MAXNB) dst[pos] = (q * 4 + ci) * 512;
                }
            }
        }
    }
    __syncthreads();
    if (tid == 0) g_ncnt[row] = min(s_cnt, MAXNB);
}

// ---------------------------------------------------------------------------
// kernelGEMM: C[8192 x 512] = Xsplit @ Bsplit (3-term bf16), K'=1536.
// Block tile 64m x 128n, grid (128, 4). 48 chunks of K=32, cp.async dbuf.
// Epilogue: fp16 pack + in-block reduced f_src/f_dst partials (per bn half).
// ---------------------------------------------------------------------------
#define ABYTES 5120
#define BUFB   13824
__global__ __launch_bounds__(256, 2) void kernelGEMM(const float* __restrict__ avec) {
    __shared__ __align__(16) char sm_ab[2 * BUFB];
    __shared__ float s_avec[512];
    __shared__ float s_fs[4][64], s_fd[4][64];

    const int bm = blockIdx.x, bn = blockIdx.y;      // bn: 0,1=h  2,3=hgc
    const int m0 = bm * 64;
    const int tid = threadIdx.x;
    const int wid = tid >> 5, lane = tid & 31;
    const int wm = wid & 1, wn = wid >> 1;           // warp tile 32m x 32n
    const uint32_t smbase = smem_u32(sm_ab);

    s_avec[tid] = avec[tid];
    s_avec[tid + 256] = avec[tid + 256];

    float cacc[2][4][4];
    #pragma unroll
    for (int i = 0; i < 2; i++)
        #pragma unroll
        for (int j = 0; j < 4; j++)
            #pragma unroll
            for (int e = 0; e < 4; e++) cacc[i][j][e] = 0.f;

    auto issue = [&](int c) {
        uint32_t buf = smbase + (uint32_t)(c & 1) * BUFB;
        int seg = c >> 4;
        const uint4* asrc = (const uint4*)((seg < 2) ? g_xh : g_xl);
        const uint4* bsrc = (const uint4*)((seg == 1) ? g_bl : g_bh);
        int kq = (c & 15) * 4;
        {   // A: 64 rows x 4 uint4 = 256 loads, 1/thread
            int r = tid >> 2, q = tid & 3;
            CPASYNC16(buf + r * 80 + q * 16, asrc + (size_t)(m0 + r) * 64 + kq + q);
        }
        int kr0 = (c & 15) * 32;
        #pragma unroll
        for (int i = 0; i < 2; i++) {                // B: 32 rows x 16 uint4
            int idx = tid + 256 * i;
            int rr = idx >> 4, q = idx & 15;
            CPASYNC16(buf + ABYTES + rr * 272 + q * 16,
                      bsrc + (size_t)(kr0 + rr) * 64 + bn * 16 + q);
        }
    };

    issue(0); CPCOMMIT();
    for (int c = 0; c < 48; c++) {
        if (c + 1 < 48) { issue(c + 1); CPCOMMIT(); CPWAIT(1); }
        else            { CPWAIT(0); }
        __syncthreads();
        uint32_t Ab = smbase + (uint32_t)(c & 1) * BUFB;
        uint32_t Bb = Ab + ABYTES;
        #pragma unroll
        for (int ks = 0; ks < 2; ks++) {
            int kk = ks * 16;
            uint32_t a[2][4], b[2][4];
            #pragma unroll
            for (int mf = 0; mf < 2; mf++)
                ldsm_x4(a[mf], Ab + (uint32_t)((wm * 32 + mf * 16 + (lane & 15)) * 80
                                               + (kk + (lane >> 4) * 8) * 2));
            #pragma unroll
            for (int ng = 0; ng < 2; ng++)
                ldsm_x4t(b[ng], Bb + (uint32_t)((kk + (lane & 15)) * 272
                                                + (wn * 32 + ng * 16 + (lane >> 4) * 8) * 2));
            #pragma unroll
            for (int mf = 0; mf < 2; mf++)
                #pragma unroll
                for (int nf = 0; nf < 4; nf++)
                    mma_bf16(cacc[mf][nf], a[mf],
                             b[nf >> 1][(nf & 1) * 2], b[nf >> 1][(nf & 1) * 2 + 1]);
        }
        __syncthreads();
    }

    // -------- epilogue: fp16 pack + staged f partials --------
    #pragma unroll
    for (int mf = 0; mf < 2; mf++) {
        #pragma unroll
        for (int half = 0; half < 2; half++) {
            int rl = wm * 32 + mf * 16 + (lane >> 2) + half * 8;   // local row
            int colbase = bn * 128 + wn * 32 + 2 * (lane & 3);
            __half2* dst = (__half2*)g_pack + ((size_t)(m0 + rl) * 512 + colbase) / 2;
            float s1 = 0.f, s2 = 0.f;
            #pragma unroll
            for (int nf = 0; nf < 4; nf++) {
                float v0 = cacc[mf][nf][half * 2 + 0];
                float v1 = cacc[mf][nf][half * 2 + 1];
                if (bn < 2) {
                    int cc = colbase + nf * 8;
                    s1 += v0 * s_avec[cc] + v1 * s_avec[cc + 1];
                    s2 += v0 * s_avec[256 + cc] + v1 * s_avec[256 + cc + 1];
                }
                dst[nf * 4] = __floats2half2_rn(v0, v1);
            }
            if (bn < 2) {
                s1 += __shfl_xor_sync(0xFFFFFFFFu, s1, 1);
                s1 += __shfl_xor_sync(0xFFFFFFFFu, s1, 2);
                s2 += __shfl_xor_sync(0xFFFFFFFFu, s2, 1);
                s2 += __shfl_xor_sync(0xFFFFFFFFu, s2, 2);
                if ((lane & 3) == 0) {
                    s_fs[wn][rl] = s1;
                    s_fd[wn][rl] = s2;
                }
            }
        }
    }
    if (bn < 2) {
        __syncthreads();
        if (tid < 64) {
            g_fsp[bn][m0 + tid] = s_fs[0][tid] + s_fs[1][tid] +
                                  s_fs[2][tid] + s_fs[3][tid];
            g_fdp[bn][m0 + tid] = s_fd[0][tid] + s_fd[1][tid] +
                                  s_fd[2][tid] + s_fd[3][tid];
        }
    }
}

// ---------------------------------------------------------------------------
// kernelB: masked softmax + fused gather (att*h + hgc). Round-7 measured
// geometry: 4-way neighbor split x 64 col-threads, uint2 loads.
// ---------------------------------------------------------------------------
__global__ __launch_bounds__(256) void kernelB(const float* __restrict__ bgc,
                                               float* __restrict__ out) {
    __shared__ int    s_idx[MAXNB];
    __shared__ float  s_e[MAXNB];
    __shared__ float  s_red[256];
    __shared__ float4 s_att[256];
    __shared__ float4 s_gc[256];

    const int row = blockIdx.x;
    const int tid = threadIdx.x;
    const int cnt = g_ncnt[row];

    if (cnt > 0) {
        const float fsi = g_fsp[0][row] + g_fsp[1][row];
        float lm = -3e38f;
        for (int k = tid; k < cnt; k += 256) {
            int joff = g_nidx[row * MAXNB + k];      // j*512
            int j = joff >> 9;
            float e = fsi + g_fdp[0][j] + g_fdp[1][j];
            e = (e > 0.f) ? e : 0.2f * e;
            s_idx[k] = joff;
            s_e[k] = e;
            lm = fmaxf(lm, e);
        }
        s_red[tid] = lm;
        __syncthreads();
        #pragma unroll
        for (int o = 128; o; o >>= 1) {
            if (tid < o) s_red[tid] = fmaxf(s_red[tid], s_red[tid + o]);
            __syncthreads();
        }
        const float mx = s_red[0];
        __syncthreads();

        float ls = 0.f;
        for (int k = tid; k < cnt; k += 256) {
            float w = expf(s_e[k] - mx);
            s_e[k] = w;
            ls += w;
        }
        s_red[tid] = ls;
        __syncthreads();
        #pragma unroll
        for (int o = 128; o; o >>= 1) {
            if (tid < o) s_red[tid] += s_red[tid + o];
            __syncthreads();
        }
        const float inv = 1.0f / s_red[0];
        __syncthreads();

        // gather: qg = neighbor subset (k % 4), tc = 4-col group
        const int qg = tid >> 6, tc = tid & 63;
        float aa0 = 0.f, aa1 = 0.f, aa2 = 0.f, aa3 = 0.f;
        float gg0 = 0.f, gg1 = 0.f, gg2 = 0.f, gg3 = 0.f;
        const __half* hp = (const __half*)g_pack;
        #pragma unroll 4
        for (int k = qg; k < cnt; k += 4) {
            int joff = s_idx[k];
            float w = s_e[k];
            uint2 hv = *(const uint2*)(hp + joff + 4 * tc);
            uint2 gv = *(const uint2*)(hp + joff + 256 + 4 * tc);
            float2 h01 = __half22float2(*(const __half2*)&hv.x);
            float2 h23 = __half22float2(*(const __half2*)&hv.y);
            float2 g01 = __half22float2(*(const __half2*)&gv.x);
            float2 g23 = __half22float2(*(const __half2*)&gv.y);
            aa0 += w * h01.x; aa1 += w * h01.y;
            aa2 += w * h23.x; aa3 += w * h23.y;
            gg0 += g01.x; gg1 += g01.y; gg2 += g23.x; gg3 += g23.y;
        }
        s_att[tid] = make_float4(aa0, aa1, aa2, aa3);
        s_gc[tid]  = make_float4(gg0, gg1, gg2, gg3);
        __syncthreads();

        if (tid < 64) {
            float4 a0 = s_att[tid],       a1 = s_att[64 + tid],
                   a2 = s_att[128 + tid], a3 = s_att[192 + tid];
            float4 g0 = s_gc[tid],        g1 = s_gc[64 + tid],
                   g2 = s_gc[128 + tid],  g3 = s_gc[192 + tid];
            float4 b = *(const float4*)(bgc + 4 * tid);
            float4 o;
            o.x = b.x + inv * (a0.x + a1.x + a2.x + a3.x) + (g0.x + g1.x + g2.x + g3.x);
            o.y = b.y + inv * (a0.y + a1.y + a2.y + a3.y) + (g0.y + g1.y + g2.y + g3.y);
            o.z = b.z + inv * (a0.z + a1.z + a2.z + a3.z) + (g0.z + g1.z + g2.z + g3.z);
            o.w = b.w + inv * (a0.w + a1.w + a2.w + a3.w) + (g0.w + g1.w + g2.w + g3.w);
            *(float4*)(out + (size_t)row * OUTF + 4 * tid) = o;
        }
    } else {
        // all-masked row: softmax uniform 1/N over all cols; gc = bias only
        const __half* hp = (const __half*)g_pack;
        float acc = 0.f;
        for (int j = 0; j < NN; j++)
            acc += __half2float(hp[(size_t)j * 512 + tid]);
        out[(size_t)row * OUTF + tid] = bgc[tid] + acc * (1.0f / (float)NN);
    }
}

// ---------------------------------------------------------------------------
extern "C" void kernel_launch(void* const* d_in, const int* in_sizes, int n_in,
                              void* d_out, int out_size) {
    const float* X   = (const float*)d_in[0];  // [8192, 512]
    const float* adj = (const float*)d_in[1];  // [8192, 8192]
    const float* W   = (const float*)d_in[2];  // [512, 256]
    const float* a   = (const float*)d_in[3];  // [512, 1]
    const float* Wgc = (const float*)d_in[4];  // [512, 256]
    const float* bgc = (const float*)d_in[5];  // [256]
    float* out = (float*)d_out;                // [8192, 256]

    // side stream + events (host objects; created once, before graph capture —
    // the harness's correctness call happens first)
    static cudaStream_t s2 = nullptr;
    static cudaEvent_t ev_fork = nullptr, ev_join = nullptr;
    if (s2 == nullptr) {
        cudaStreamCreateWithFlags(&s2, cudaStreamNonBlocking);
        cudaEventCreateWithFlags(&ev_fork, cudaEventDisableTiming);
        cudaEventCreateWithFlags(&ev_join, cudaEventDisableTiming);
    }

    // fork: scan (DRAM-bound) runs on s2, concurrently with prep+GEMM (tensor)
    cudaEventRecord(ev_fork, 0);
    cudaStreamWaitEvent(s2, ev_fork, 0);

    kernelScan<<<NN, 256, 0, s2>>>(adj);

    prepX<<<NN * INF / 4 / 256, 256>>>(X);
    prepB<<<512, 256>>>(W, Wgc);
    kernelGEMM<<<dim3(128, 4), 256>>>(a);

    // join: kernelB needs both the scan output and the GEMM output
    cudaEventRecord(ev_join, s2);
    cudaStreamWaitEvent(0, ev_join, 0);

    kernelB<<<NN, 256>>>(bgc, out);
}

// round 13
// speedup vs baseline: 1.2297x; 1.0934x over previous
#include <cuda_runtime.h>
#include <cuda_fp16.h>
#include <cuda_bf16.h>
#include <cstdint>

#define NN    8192
#define INF   512
#define OUTF  256
#define MAXNB 1024

// ---------------- scratch (__device__ globals: allocation-free rule) --------
__device__ float          g_fs[NN];
__device__ float          g_fd[NN];
// pack layout per row: 64 groups x 16B; group g = {h[4g..4g+3], hgc[4g..4g+3]}
__device__ __half         g_pack[NN * 512];
__device__ int            g_ncnt[NN];
__device__ int            g_nidx[NN * MAXNB]; // pre-scaled j*512 (half units)
__device__ __nv_bfloat16  g_xh[NN * INF];   // bf16 hi of X  [row][512]
__device__ __nv_bfloat16  g_xl[NN * INF];   // bf16 lo of X
__device__ __nv_bfloat16  g_bh[INF * 512];  // [k][512] = W | Wgc (hi)
__device__ __nv_bfloat16  g_bl[INF * 512];  // lo

// ---------------- helpers ---------------------------------------------------
__device__ __forceinline__ uint32_t smem_u32(const void* p) {
    uint32_t a;
    asm("{ .reg .u64 t; cvta.to.shared.u64 t, %1; cvt.u32.u64 %0, t; }"
        : "=r"(a) : "l"(p));
    return a;
}
#define CPASYNC16(dst, src) \
    asm volatile("cp.async.cg.shared.global [%0], [%1], 16;" \
                 :: "r"(dst), "l"(src) : "memory")
#define CPCOMMIT() asm volatile("cp.async.commit_group;" ::: "memory")
#define CPWAIT(n)  asm volatile("cp.async.wait_group %0;" :: "n"(n) : "memory")

__device__ __forceinline__ void ldsm_x4(uint32_t (&r)[4], uint32_t addr) {
    asm volatile("ldmatrix.sync.aligned.m8n8.x4.shared.b16 {%0,%1,%2,%3}, [%4];"
                 : "=r"(r[0]), "=r"(r[1]), "=r"(r[2]), "=r"(r[3]) : "r"(addr));
}
__device__ __forceinline__ void ldsm_x4t(uint32_t (&r)[4], uint32_t addr) {
    asm volatile("ldmatrix.sync.aligned.m8n8.x4.trans.shared.b16 {%0,%1,%2,%3}, [%4];"
                 : "=r"(r[0]), "=r"(r[1]), "=r"(r[2]), "=r"(r[3]) : "r"(addr));
}
__device__ __forceinline__ void mma_bf16(float* c, const uint32_t* a,
                                         uint32_t b0, uint32_t b1) {
    asm volatile("mma.sync.aligned.m16n8k16.row.col.f32.bf16.bf16.f32 "
                 "{%0,%1,%2,%3}, {%4,%5,%6,%7}, {%8,%9}, {%0,%1,%2,%3};"
                 : "+f"(c[0]), "+f"(c[1]), "+f"(c[2]), "+f"(c[3])
                 : "r"(a[0]), "r"(a[1]), "r"(a[2]), "r"(a[3]), "r"(b0), "r"(b1));
}

// ---------------------------------------------------------------------------
// prepX: X fp32 -> (Xh, Xl) bf16 split
// ---------------------------------------------------------------------------
__global__ __launch_bounds__(256) void prepX(const float* __restrict__ X) {
    int i = blockIdx.x * 256 + threadIdx.x;          // float4 index
    float4 v = ((const float4*)X)[i];
    __nv_bfloat16 hv[4], lv[4];
    float f[4] = {v.x, v.y, v.z, v.w};
    #pragma unroll
    for (int j = 0; j < 4; j++) {
        hv[j] = __float2bfloat16_rn(f[j]);
        lv[j] = __float2bfloat16_rn(f[j] - __bfloat162float(hv[j]));
    }
    *(uint2*)(g_xh + (size_t)i * 4) = *(uint2*)hv;
    *(uint2*)(g_xl + (size_t)i * 4) = *(uint2*)lv;
}

// ---------------------------------------------------------------------------
// prepB: W,Wgc [512][256] fp32 -> g_bh/g_bl [512][512] bf16
// ---------------------------------------------------------------------------
__global__ __launch_bounds__(256) void prepB(const float* __restrict__ W,
                                             const float* __restrict__ Wgc) {
    int k = blockIdx.x, n = threadIdx.x;
    float w = W[k * 256 + n];
    __nv_bfloat16 hb = __float2bfloat16_rn(w);
    g_bh[k * 512 + n] = hb;
    g_bl[k * 512 + n] = __float2bfloat16_rn(w - __bfloat162float(hb));
    float wg = Wgc[k * 256 + n];
    hb = __float2bfloat16_rn(wg);
    g_bh[k * 512 + 256 + n] = hb;
    g_bl[k * 512 + 256 + n] = __float2bfloat16_rn(wg - __bfloat162float(hb));
}

// ---------------------------------------------------------------------------
// kernelScan: streaming adjacency scan, ballot compaction -> g_nidx/g_ncnt
// ---------------------------------------------------------------------------
__global__ __launch_bounds__(256) void kernelScan(const float* __restrict__ adj) {
    __shared__ int s_cnt;
    const int row = blockIdx.x;
    const int tid = threadIdx.x;
    const int lane = tid & 31;
    if (tid == 0) s_cnt = 0;
    __syncthreads();

    const float4* arow = (const float4*)(adj + (size_t)row * NN);
    float4 v[8];
    #pragma unroll
    for (int r = 0; r < 8; r++) v[r] = arow[tid + 256 * r];

    int* dst = g_nidx + row * MAXNB;
    #pragma unroll
    for (int r = 0; r < 8; r++) {
        int q = tid + 256 * r;
        float comp[4] = {v[r].x, v[r].y, v[r].z, v[r].w};
        #pragma unroll
        for (int ci = 0; ci < 4; ci++) {
            bool hit = comp[ci] > 0.f;
            unsigned m = __ballot_sync(0xFFFFFFFFu, hit);
            if (m) {
                int base;
                if (lane == 0) base = atomicAdd(&s_cnt, __popc(m));
                base = __shfl_sync(0xFFFFFFFFu, base, 0);
                if (hit) {
                    int pos = base + __popc(m & ((1u << lane) - 1u));
                    if (pos < MAXNB) dst[pos] = (q * 4 + ci) * 512;
                }
            }
        }
    }
    __syncthreads();
    if (tid == 0) g_ncnt[row] = min(s_cnt, MAXNB);
}

// ---------------------------------------------------------------------------
// kernelGEMM: C[8192 x 512] = Xsplit @ Bsplit (3-term bf16), K'=1536.
// Block 64m x 256n, grid (128, 2) = ONE wave at 2 CTAs/SM. Warp tile 32x64.
// bn=0 covers ALL of h's columns -> complete f_src/f_dst in-block.
// ---------------------------------------------------------------------------
#define ABYTES 5120
#define BSTRIDE 528
#define BUFB   (ABYTES + 32 * BSTRIDE)   // 5120 + 16896 = 22016
__global__ __launch_bounds__(256, 2) void kernelGEMM(const float* __restrict__ avec) {
    __shared__ __align__(16) char sm_ab[2 * BUFB];
    __shared__ float s_avec[512];
    __shared__ float s_fs[4][64], s_fd[4][64];

    const int bm = blockIdx.x, bn = blockIdx.y;      // bn: 0=h, 1=hgc
    const int m0 = bm * 64;
    const int tid = threadIdx.x;
    const int wid = tid >> 5, lane = tid & 31;
    const int wm = wid & 1, wn = wid >> 1;           // warp tile 32m x 64n
    const uint32_t smbase = smem_u32(sm_ab);

    s_avec[tid] = avec[tid];
    s_avec[tid + 256] = avec[tid + 256];

    float cacc[2][8][4];
    #pragma unroll
    for (int i = 0; i < 2; i++)
        #pragma unroll
        for (int j = 0; j < 8; j++)
            #pragma unroll
            for (int e = 0; e < 4; e++) cacc[i][j][e] = 0.f;

    auto issue = [&](int c) {
        uint32_t buf = smbase + (uint32_t)(c & 1) * BUFB;
        int seg = c >> 4;
        const uint4* asrc = (const uint4*)((seg < 2) ? g_xh : g_xl);
        const uint4* bsrc = (const uint4*)((seg == 1) ? g_bl : g_bh);
        int kq = (c & 15) * 4;
        {   // A: 64 rows x 4 uint4, 1/thread
            int r = tid >> 2, q = tid & 3;
            CPASYNC16(buf + r * 80 + q * 16, asrc + (size_t)(m0 + r) * 64 + kq + q);
        }
        int kr0 = (c & 15) * 32;
        #pragma unroll
        for (int i = 0; i < 4; i++) {                // B: 32 rows x 32 uint4
            int idx = tid + 256 * i;
            int rr = idx >> 5, q = idx & 31;
            CPASYNC16(buf + ABYTES + rr * BSTRIDE + q * 16,
                      bsrc + (size_t)(kr0 + rr) * 64 + bn * 32 + q);
        }
    };

    issue(0); CPCOMMIT();
    for (int c = 0; c < 48; c++) {
        if (c + 1 < 48) { issue(c + 1); CPCOMMIT(); CPWAIT(1); }
        else            { CPWAIT(0); }
        __syncthreads();
        uint32_t Ab = smbase + (uint32_t)(c & 1) * BUFB;
        uint32_t Bb = Ab + ABYTES;
        #pragma unroll
        for (int ks = 0; ks < 2; ks++) {
            int kk = ks * 16;
            uint32_t a[2][4], b[4][4];
            #pragma unroll
            for (int mf = 0; mf < 2; mf++)
                ldsm_x4(a[mf], Ab + (uint32_t)((wm * 32 + mf * 16 + (lane & 15)) * 80
                                               + (kk + (lane >> 4) * 8) * 2));
            #pragma unroll
            for (int ng = 0; ng < 4; ng++)
                ldsm_x4t(b[ng], Bb + (uint32_t)((kk + (lane & 15)) * BSTRIDE
                                                + (wn * 64 + ng * 16 + (lane >> 4) * 8) * 2));
            #pragma unroll
            for (int mf = 0; mf < 2; mf++)
                #pragma unroll
                for (int nf = 0; nf < 8; nf++)
                    mma_bf16(cacc[mf][nf], a[mf],
                             b[nf >> 1][(nf & 1) * 2], b[nf >> 1][(nf & 1) * 2 + 1]);
        }
        __syncthreads();
    }

    // -------- epilogue: interleaved fp16 pack + complete f (bn==0) ----------
    const uint32_t gsub = (bn == 0) ? 0u : 8u;       // byte offset within group
    #pragma unroll
    for (int mf = 0; mf < 2; mf++) {
        #pragma unroll
        for (int half = 0; half < 2; half++) {
            int rl = wm * 32 + mf * 16 + (lane >> 2) + half * 8;   // local row
            float s1 = 0.f, s2 = 0.f;
            char* rowp = (char*)g_pack + (size_t)(m0 + rl) * 1024;
            #pragma unroll
            for (int nf = 0; nf < 8; nf++) {
                float v0 = cacc[mf][nf][half * 2 + 0];
                float v1 = cacc[mf][nf][half * 2 + 1];
                int c = wn * 64 + nf * 8 + 2 * (lane & 3);
                if (bn == 0) {
                    s1 += v0 * s_avec[c] + v1 * s_avec[c + 1];
                    s2 += v0 * s_avec[256 + c] + v1 * s_avec[256 + c + 1];
                }
                *(__half2*)(rowp + (c >> 2) * 16 + gsub + (c & 3) * 2) =
                    __floats2half2_rn(v0, v1);
            }
            if (bn == 0) {
                s1 += __shfl_xor_sync(0xFFFFFFFFu, s1, 1);
                s1 += __shfl_xor_sync(0xFFFFFFFFu, s1, 2);
                s2 += __shfl_xor_sync(0xFFFFFFFFu, s2, 1);
                s2 += __shfl_xor_sync(0xFFFFFFFFu, s2, 2);
                if ((lane & 3) == 0) {
                    s_fs[wn][rl] = s1;
                    s_fd[wn][rl] = s2;
                }
            }
        }
    }
    if (bn == 0) {
        __syncthreads();
        if (tid < 64) {
            g_fs[m0 + tid] = s_fs[0][tid] + s_fs[1][tid] +
                             s_fs[2][tid] + s_fs[3][tid];
            g_fd[m0 + tid] = s_fd[0][tid] + s_fd[1][tid] +
                             s_fd[2][tid] + s_fd[3][tid];
        }
    }
}

// ---------------------------------------------------------------------------
// kernelB: masked softmax + fused gather. 4-way neighbor split x 64 threads,
// ONE uint4 per (neighbor, thread) via the interleaved pack layout.
// ---------------------------------------------------------------------------
__global__ __launch_bounds__(256) void kernelB(const float* __restrict__ bgc,
                                               float* __restrict__ out) {
    __shared__ int    s_idx[MAXNB];
    __shared__ float  s_e[MAXNB];
    __shared__ float  s_red[256];
    __shared__ float4 s_att[256];
    __shared__ float4 s_gc[256];

    const int row = blockIdx.x;
    const int tid = threadIdx.x;
    const int cnt = g_ncnt[row];

    if (cnt > 0) {
        const float fsi = g_fs[row];
        float lm = -3e38f;
        for (int k = tid; k < cnt; k += 256) {
            int joff = g_nidx[row * MAXNB + k];      // j*512
            float e = fsi + g_fd[joff >> 9];
            e = (e > 0.f) ? e : 0.2f * e;
            s_idx[k] = joff;
            s_e[k] = e;
            lm = fmaxf(lm, e);
        }
        s_red[tid] = lm;
        __syncthreads();
        #pragma unroll
        for (int o = 128; o; o >>= 1) {
            if (tid < o) s_red[tid] = fmaxf(s_red[tid], s_red[tid + o]);
            __syncthreads();
        }
        const float mx = s_red[0];
        __syncthreads();

        float ls = 0.f;
        for (int k = tid; k < cnt; k += 256) {
            float w = expf(s_e[k] - mx);
            s_e[k] = w;
            ls += w;
        }
        s_red[tid] = ls;
        __syncthreads();
        #pragma unroll
        for (int o = 128; o; o >>= 1) {
            if (tid < o) s_red[tid] += s_red[tid + o];
            __syncthreads();
        }
        const float inv = 1.0f / s_red[0];
        __syncthreads();

        // gather: qg = neighbor subset (k % 4), tc = 4-col group; 1 uint4 each
        const int qg = tid >> 6, tc = tid & 63;
        float aa0 = 0.f, aa1 = 0.f, aa2 = 0.f, aa3 = 0.f;
        float gg0 = 0.f, gg1 = 0.f, gg2 = 0.f, gg3 = 0.f;
        const __half* hp = (const __half*)g_pack;
        #pragma unroll 4
        for (int k = qg; k < cnt; k += 4) {
            float w = s_e[k];
            uint4 pv = *(const uint4*)(hp + s_idx[k] + 8 * tc);
            float2 h01 = __half22float2(*(const __half2*)&pv.x);
            float2 h23 = __half22float2(*(const __half2*)&pv.y);
            float2 g01 = __half22float2(*(const __half2*)&pv.z);
            float2 g23 = __half22float2(*(const __half2*)&pv.w);
            aa0 += w * h01.x; aa1 += w * h01.y;
            aa2 += w * h23.x; aa3 += w * h23.y;
            gg0 += g01.x; gg1 += g01.y; gg2 += g23.x; gg3 += g23.y;
        }
        s_att[tid] = make_float4(aa0, aa1, aa2, aa3);
        s_gc[tid]  = make_float4(gg0, gg1, gg2, gg3);
        __syncthreads();

        if (tid < 64) {
            float4 a0 = s_att[tid],       a1 = s_att[64 + tid],
                   a2 = s_att[128 + tid], a3 = s_att[192 + tid];
            float4 g0 = s_gc[tid],        g1 = s_gc[64 + tid],
                   g2 = s_gc[128 + tid],  g3 = s_gc[192 + tid];
            float4 b = *(const float4*)(bgc + 4 * tid);
            float4 o;
            o.x = b.x + inv * (a0.x + a1.x + a2.x + a3.x) + (g0.x + g1.x + g2.x + g3.x);
            o.y = b.y + inv * (a0.y + a1.y + a2.y + a3.y) + (g0.y + g1.y + g2.y + g3.y);
            o.z = b.z + inv * (a0.z + a1.z + a2.z + a3.z) + (g0.z + g1.z + g2.z + g3.z);
            o.w = b.w + inv * (a0.w + a1.w + a2.w + a3.w) + (g0.w + g1.w + g2.w + g3.w);
            *(float4*)(out + (size_t)row * OUTF + 4 * tid) = o;
        }
    } else {
        // all-masked row: softmax uniform 1/N over all cols; gc = bias only
        const __half* hp = (const __half*)g_pack;
        float acc = 0.f;
        int hidx = (tid >> 2) * 8 + (tid & 3);       // col tid in interleaved layout
        for (int j = 0; j < NN; j++)
            acc += __half2float(hp[(size_t)j * 512 + hidx]);
        out[(size_t)row * OUTF + tid] = bgc[tid] + acc * (1.0f / (float)NN);
    }
}

// ---------------------------------------------------------------------------
extern "C" void kernel_launch(void* const* d_in, const int* in_sizes, int n_in,
                              void* d_out, int out_size) {
    const float* X   = (const float*)d_in[0];  // [8192, 512]
    const float* adj = (const float*)d_in[1];  // [8192, 8192]
    const float* W   = (const float*)d_in[2];  // [512, 256]
    const float* a   = (const float*)d_in[3];  // [512, 1]
    const float* Wgc = (const float*)d_in[4];  // [512, 256]
    const float* bgc = (const float*)d_in[5];  // [256]
    float* out = (float*)d_out;                // [8192, 256]

    static cudaStream_t s2 = nullptr;
    static cudaEvent_t ev_fork = nullptr, ev_join = nullptr;
    if (s2 == nullptr) {
        cudaStreamCreateWithFlags(&s2, cudaStreamNonBlocking);
        cudaEventCreateWithFlags(&ev_fork, cudaEventDisableTiming);
        cudaEventCreateWithFlags(&ev_join, cudaEventDisableTiming);
    }

    // GEMM path submitted FIRST so its single co-resident wave grabs SM slots,
    // then the scan fills the remaining thread slots -> true DRAM/tensor overlap.
    cudaEventRecord(ev_fork, 0);
    cudaStreamWaitEvent(s2, ev_fork, 0);

    prepX<<<NN * INF / 4 / 256, 256>>>(X);
    prepB<<<512, 256>>>(W, Wgc);
    kernelGEMM<<<dim3(128, 2), 256>>>(a);

    kernelScan<<<NN, 256, 0, s2>>>(adj);

    cudaEventRecord(ev_join, s2);
    cudaStreamWaitEvent(0, ev_join, 0);

    kernelB<<<NN, 256>>>(bgc, out);
}

// round 14
// speedup vs baseline: 1.3525x; 1.0999x over previous
#include <cuda_runtime.h>
#include <cuda_fp16.h>
#include <cuda_bf16.h>
#include <cstdint>

#define NN    8192
#define INF   512
#define OUTF  256
#define MAXNB 1024

// ---------------- scratch (__device__ globals: allocation-free rule) --------
__device__ float          g_fs[NN];
__device__ float          g_fd[NN];
// pack layout per row: 64 groups x 16B; group g = {h[4g..4g+3], hgc[4g..4g+3]}
__device__ __half         g_pack[NN * 512];
__device__ int            g_ncnt[NN];
__device__ int            g_nidx[NN * MAXNB]; // pre-scaled j*512 (half units)
__device__ __nv_bfloat16  g_xh[NN * INF];   // bf16 hi of X  [row][512]
__device__ __nv_bfloat16  g_xl[NN * INF];   // bf16 lo of X
__device__ __nv_bfloat16  g_bh[INF * 512];  // [k][512] = W | Wgc (hi)
__device__ __nv_bfloat16  g_bl[INF * 512];  // lo

// ---------------- helpers ---------------------------------------------------
__device__ __forceinline__ uint32_t smem_u32(const void* p) {
    uint32_t a;
    asm("{ .reg .u64 t; cvta.to.shared.u64 t, %1; cvt.u32.u64 %0, t; }"
        : "=r"(a) : "l"(p));
    return a;
}
#define CPASYNC16(dst, src) \
    asm volatile("cp.async.cg.shared.global [%0], [%1], 16;" \
                 :: "r"(dst), "l"(src) : "memory")
#define CPCOMMIT() asm volatile("cp.async.commit_group;" ::: "memory")
#define CPWAIT(n)  asm volatile("cp.async.wait_group %0;" :: "n"(n) : "memory")

__device__ __forceinline__ void ldsm_x4(uint32_t (&r)[4], uint32_t addr) {
    asm volatile("ldmatrix.sync.aligned.m8n8.x4.shared.b16 {%0,%1,%2,%3}, [%4];"
                 : "=r"(r[0]), "=r"(r[1]), "=r"(r[2]), "=r"(r[3]) : "r"(addr));
}
__device__ __forceinline__ void ldsm_x4t(uint32_t (&r)[4], uint32_t addr) {
    asm volatile("ldmatrix.sync.aligned.m8n8.x4.trans.shared.b16 {%0,%1,%2,%3}, [%4];"
                 : "=r"(r[0]), "=r"(r[1]), "=r"(r[2]), "=r"(r[3]) : "r"(addr));
}
__device__ __forceinline__ void mma_bf16(float* c, const uint32_t* a,
                                         uint32_t b0, uint32_t b1) {
    asm volatile("mma.sync.aligned.m16n8k16.row.col.f32.bf16.bf16.f32 "
                 "{%0,%1,%2,%3}, {%4,%5,%6,%7}, {%8,%9}, {%0,%1,%2,%3};"
                 : "+f"(c[0]), "+f"(c[1]), "+f"(c[2]), "+f"(c[3])
                 : "r"(a[0]), "r"(a[1]), "r"(a[2]), "r"(a[3]), "r"(b0), "r"(b1));
}

// ---------------------------------------------------------------------------
// prepX: X fp32 -> (Xh, Xl) bf16 split
// ---------------------------------------------------------------------------
__global__ __launch_bounds__(256) void prepX(const float* __restrict__ X) {
    int i = blockIdx.x * 256 + threadIdx.x;          // float4 index
    float4 v = ((const float4*)X)[i];
    __nv_bfloat16 hv[4], lv[4];
    float f[4] = {v.x, v.y, v.z, v.w};
    #pragma unroll
    for (int j = 0; j < 4; j++) {
        hv[j] = __float2bfloat16_rn(f[j]);
        lv[j] = __float2bfloat16_rn(f[j] - __bfloat162float(hv[j]));
    }
    *(uint2*)(g_xh + (size_t)i * 4) = *(uint2*)hv;
    *(uint2*)(g_xl + (size_t)i * 4) = *(uint2*)lv;
}

// ---------------------------------------------------------------------------
// prepB: W,Wgc [512][256] fp32 -> g_bh/g_bl [512][512] bf16
// ---------------------------------------------------------------------------
__global__ __launch_bounds__(256) void prepB(const float* __restrict__ W,
                                             const float* __restrict__ Wgc) {
    int k = blockIdx.x, n = threadIdx.x;
    float w = W[k * 256 + n];
    __nv_bfloat16 hb = __float2bfloat16_rn(w);
    g_bh[k * 512 + n] = hb;
    g_bl[k * 512 + n] = __float2bfloat16_rn(w - __bfloat162float(hb));
    float wg = Wgc[k * 256 + n];
    hb = __float2bfloat16_rn(wg);
    g_bh[k * 512 + 256 + n] = hb;
    g_bl[k * 512 + 256 + n] = __float2bfloat16_rn(wg - __bfloat162float(hb));
}

// ---------------------------------------------------------------------------
// kernelScan: streaming adjacency scan. Two front-batched 4xfloat4 rounds
// (MLP=4 each) keep regs <=32 so __launch_bounds__(256,8) gives 100% occ.
// ---------------------------------------------------------------------------
__global__ __launch_bounds__(256, 8) void kernelScan(const float* __restrict__ adj) {
    __shared__ int s_cnt;
    const int row = blockIdx.x;
    const int tid = threadIdx.x;
    const int lane = tid & 31;
    if (tid == 0) s_cnt = 0;
    __syncthreads();

    const float4* arow = (const float4*)(adj + (size_t)row * NN);
    int* dst = g_nidx + row * MAXNB;

    #pragma unroll
    for (int half = 0; half < 2; half++) {
        float4 v[4];
        #pragma unroll
        for (int r = 0; r < 4; r++) v[r] = arow[tid + 256 * (half * 4 + r)];
        #pragma unroll
        for (int r = 0; r < 4; r++) {
            int q = tid + 256 * (half * 4 + r);
            float comp[4] = {v[r].x, v[r].y, v[r].z, v[r].w};
            #pragma unroll
            for (int ci = 0; ci < 4; ci++) {
                bool hit = comp[ci] > 0.f;
                unsigned m = __ballot_sync(0xFFFFFFFFu, hit);
                if (m) {
                    int base;
                    if (lane == 0) base = atomicAdd(&s_cnt, __popc(m));
                    base = __shfl_sync(0xFFFFFFFFu, base, 0);
                    if (hit) {
                        int pos = base + __popc(m & ((1u << lane) - 1u));
                        if (pos < MAXNB) dst[pos] = (q * 4 + ci) * 512;
                    }
                }
            }
        }
    }
    __syncthreads();
    if (tid == 0) g_ncnt[row] = min(s_cnt, MAXNB);
}

// ---------------------------------------------------------------------------
// kernelGEMM: C[8192 x 512] = Xsplit @ Bsplit (3-term bf16), K'=1536.
// Block 64m x 256n, grid (128, 2) = ONE wave at 2 CTAs/SM. Warp tile 32x64.
// bn=0 covers ALL of h's columns -> complete f_src/f_dst in-block.
// ---------------------------------------------------------------------------
#define ABYTES 5120
#define BSTRIDE 528
#define BUFB   (ABYTES + 32 * BSTRIDE)   // 22016
__global__ __launch_bounds__(256, 2) void kernelGEMM(const float* __restrict__ avec) {
    __shared__ __align__(16) char sm_ab[2 * BUFB];
    __shared__ float s_avec[512];
    __shared__ float s_fs[4][64], s_fd[4][64];

    const int bm = blockIdx.x, bn = blockIdx.y;      // bn: 0=h, 1=hgc
    const int m0 = bm * 64;
    const int tid = threadIdx.x;
    const int wid = tid >> 5, lane = tid & 31;
    const int wm = wid & 1, wn = wid >> 1;           // warp tile 32m x 64n
    const uint32_t smbase = smem_u32(sm_ab);

    s_avec[tid] = avec[tid];
    s_avec[tid + 256] = avec[tid + 256];

    float cacc[2][8][4];
    #pragma unroll
    for (int i = 0; i < 2; i++)
        #pragma unroll
        for (int j = 0; j < 8; j++)
            #pragma unroll
            for (int e = 0; e < 4; e++) cacc[i][j][e] = 0.f;

    auto issue = [&](int c) {
        uint32_t buf = smbase + (uint32_t)(c & 1) * BUFB;
        int seg = c >> 4;
        const uint4* asrc = (const uint4*)((seg < 2) ? g_xh : g_xl);
        const uint4* bsrc = (const uint4*)((seg == 1) ? g_bl : g_bh);
        int kq = (c & 15) * 4;
        {   // A: 64 rows x 4 uint4, 1/thread
            int r = tid >> 2, q = tid & 3;
            CPASYNC16(buf + r * 80 + q * 16, asrc + (size_t)(m0 + r) * 64 + kq + q);
        }
        int kr0 = (c & 15) * 32;
        #pragma unroll
        for (int i = 0; i < 4; i++) {                // B: 32 rows x 32 uint4
            int idx = tid + 256 * i;
            int rr = idx >> 5, q = idx & 31;
            CPASYNC16(buf + ABYTES + rr * BSTRIDE + q * 16,
                      bsrc + (size_t)(kr0 + rr) * 64 + bn * 32 + q);
        }
    };

    issue(0); CPCOMMIT();
    for (int c = 0; c < 48; c++) {
        if (c + 1 < 48) { issue(c + 1); CPCOMMIT(); CPWAIT(1); }
        else            { CPWAIT(0); }
        __syncthreads();
        uint32_t Ab = smbase + (uint32_t)(c & 1) * BUFB;
        uint32_t Bb = Ab + ABYTES;
        #pragma unroll
        for (int ks = 0; ks < 2; ks++) {
            int kk = ks * 16;
            uint32_t a[2][4], b[4][4];
            #pragma unroll
            for (int mf = 0; mf < 2; mf++)
                ldsm_x4(a[mf], Ab + (uint32_t)((wm * 32 + mf * 16 + (lane & 15)) * 80
                                               + (kk + (lane >> 4) * 8) * 2));
            #pragma unroll
            for (int ng = 0; ng < 4; ng++)
                ldsm_x4t(b[ng], Bb + (uint32_t)((kk + (lane & 15)) * BSTRIDE
                                                + (wn * 64 + ng * 16 + (lane >> 4) * 8) * 2));
            #pragma unroll
            for (int mf = 0; mf < 2; mf++)
                #pragma unroll
                for (int nf = 0; nf < 8; nf++)
                    mma_bf16(cacc[mf][nf], a[mf],
                             b[nf >> 1][(nf & 1) * 2], b[nf >> 1][(nf & 1) * 2 + 1]);
        }
        __syncthreads();
    }

    // -------- epilogue: interleaved fp16 pack + complete f (bn==0) ----------
    const uint32_t gsub = (bn == 0) ? 0u : 8u;       // byte offset within group
    #pragma unroll
    for (int mf = 0; mf < 2; mf++) {
        #pragma unroll
        for (int half = 0; half < 2; half++) {
            int rl = wm * 32 + mf * 16 + (lane >> 2) + half * 8;   // local row
            float s1 = 0.f, s2 = 0.f;
            char* rowp = (char*)g_pack + (size_t)(m0 + rl) * 1024;
            #pragma unroll
            for (int nf = 0; nf < 8; nf++) {
                float v0 = cacc[mf][nf][half * 2 + 0];
                float v1 = cacc[mf][nf][half * 2 + 1];
                int c = wn * 64 + nf * 8 + 2 * (lane & 3);
                if (bn == 0) {
                    s1 += v0 * s_avec[c] + v1 * s_avec[c + 1];
                    s2 += v0 * s_avec[256 + c] + v1 * s_avec[256 + c + 1];
                }
                *(__half2*)(rowp + (c >> 2) * 16 + gsub + (c & 3) * 2) =
                    __floats2half2_rn(v0, v1);
            }
            if (bn == 0) {
                s1 += __shfl_xor_sync(0xFFFFFFFFu, s1, 1);
                s1 += __shfl_xor_sync(0xFFFFFFFFu, s1, 2);
                s2 += __shfl_xor_sync(0xFFFFFFFFu, s2, 1);
                s2 += __shfl_xor_sync(0xFFFFFFFFu, s2, 2);
                if ((lane & 3) == 0) {
                    s_fs[wn][rl] = s1;
                    s_fd[wn][rl] = s2;
                }
            }
        }
    }
    if (bn == 0) {
        __syncthreads();
        if (tid < 64) {
            g_fs[m0 + tid] = s_fs[0][tid] + s_fs[1][tid] +
                             s_fs[2][tid] + s_fs[3][tid];
            g_fd[m0 + tid] = s_fd[0][tid] + s_fd[1][tid] +
                             s_fd[2][tid] + s_fd[3][tid];
        }
    }
}

// ---------------------------------------------------------------------------
// kernelB: masked softmax + fused gather. 4-way neighbor split x 64 threads,
// ONE uint4 per (neighbor, thread) via the interleaved pack layout.
// ---------------------------------------------------------------------------
__global__ __launch_bounds__(256) void kernelB(const float* __restrict__ bgc,
                                               float* __restrict__ out) {
    __shared__ int    s_idx[MAXNB];
    __shared__ float  s_e[MAXNB];
    __shared__ float  s_red[256];
    __shared__ float4 s_att[256];
    __shared__ float4 s_gc[256];

    const int row = blockIdx.x;
    const int tid = threadIdx.x;
    const int cnt = g_ncnt[row];

    if (cnt > 0) {
        const float fsi = g_fs[row];
        float lm = -3e38f;
        for (int k = tid; k < cnt; k += 256) {
            int joff = g_nidx[row * MAXNB + k];      // j*512
            float e = fsi + g_fd[joff >> 9];
            e = (e > 0.f) ? e : 0.2f * e;
            s_idx[k] = joff;
            s_e[k] = e;
            lm = fmaxf(lm, e);
        }
        s_red[tid] = lm;
        __syncthreads();
        #pragma unroll
        for (int o = 128; o; o >>= 1) {
            if (tid < o) s_red[tid] = fmaxf(s_red[tid], s_red[tid + o]);
            __syncthreads();
        }
        const float mx = s_red[0];
        __syncthreads();

        float ls = 0.f;
        for (int k = tid; k < cnt; k += 256) {
            float w = expf(s_e[k] - mx);
            s_e[k] = w;
            ls += w;
        }
        s_red[tid] = ls;
        __syncthreads();
        #pragma unroll
        for (int o = 128; o; o >>= 1) {
            if (tid < o) s_red[tid] += s_red[tid + o];
            __syncthreads();
        }
        const float inv = 1.0f / s_red[0];
        __syncthreads();

        // gather: qg = neighbor subset (k % 4), tc = 4-col group; 1 uint4 each
        const int qg = tid >> 6, tc = tid & 63;
        float aa0 = 0.f, aa1 = 0.f, aa2 = 0.f, aa3 = 0.f;
        float gg0 = 0.f, gg1 = 0.f, gg2 = 0.f, gg3 = 0.f;
        const __half* hp = (const __half*)g_pack;
        #pragma unroll 4
        for (int k = qg; k < cnt; k += 4) {
            float w = s_e[k];
            uint4 pv = *(const uint4*)(hp + s_idx[k] + 8 * tc);
            float2 h01 = __half22float2(*(const __half2*)&pv.x);
            float2 h23 = __half22float2(*(const __half2*)&pv.y);
            float2 g01 = __half22float2(*(const __half2*)&pv.z);
            float2 g23 = __half22float2(*(const __half2*)&pv.w);
            aa0 += w * h01.x; aa1 += w * h01.y;
            aa2 += w * h23.x; aa3 += w * h23.y;
            gg0 += g01.x; gg1 += g01.y; gg2 += g23.x; gg3 += g23.y;
        }
        s_att[tid] = make_float4(aa0, aa1, aa2, aa3);
        s_gc[tid]  = make_float4(gg0, gg1, gg2, gg3);
        __syncthreads();

        if (tid < 64) {
            float4 a0 = s_att[tid],       a1 = s_att[64 + tid],
                   a2 = s_att[128 + tid], a3 = s_att[192 + tid];
            float4 g0 = s_gc[tid],        g1 = s_gc[64 + tid],
                   g2 = s_gc[128 + tid],  g3 = s_gc[192 + tid];
            float4 b = *(const float4*)(bgc + 4 * tid);
            float4 o;
            o.x = b.x + inv * (a0.x + a1.x + a2.x + a3.x) + (g0.x + g1.x + g2.x + g3.x);
            o.y = b.y + inv * (a0.y + a1.y + a2.y + a3.y) + (g0.y + g1.y + g2.y + g3.y);
            o.z = b.z + inv * (a0.z + a1.z + a2.z + a3.z) + (g0.z + g1.z + g2.z + g3.z);
            o.w = b.w + inv * (a0.w + a1.w + a2.w + a3.w) + (g0.w + g1.w + g2.w + g3.w);
            *(float4*)(out + (size_t)row * OUTF + 4 * tid) = o;
        }
    } else {
        // all-masked row: softmax uniform 1/N over all cols; gc = bias only
        const __half* hp = (const __half*)g_pack;
        float acc = 0.f;
        int hidx = (tid >> 2) * 8 + (tid & 3);       // col tid in interleaved layout
        for (int j = 0; j < NN; j++)
            acc += __half2float(hp[(size_t)j * 512 + hidx]);
        out[(size_t)row * OUTF + tid] = bgc[tid] + acc * (1.0f / (float)NN);
    }
}

// ---------------------------------------------------------------------------
extern "C" void kernel_launch(void* const* d_in, const int* in_sizes, int n_in,
                              void* d_out, int out_size) {
    const float* X   = (const float*)d_in[0];  // [8192, 512]
    const float* adj = (const float*)d_in[1];  // [8192, 8192]
    const float* W   = (const float*)d_in[2];  // [512, 256]
    const float* a   = (const float*)d_in[3];  // [512, 1]
    const float* Wgc = (const float*)d_in[4];  // [512, 256]
    const float* bgc = (const float*)d_in[5];  // [256]
    float* out = (float*)d_out;                // [8192, 256]

    static cudaStream_t s2 = nullptr;
    static cudaEvent_t ev_fork = nullptr, ev_join = nullptr;
    if (s2 == nullptr) {
        int lo, hi;
        cudaDeviceGetStreamPriorityRange(&lo, &hi);  // lo = LOWEST priority value
        cudaStreamCreateWithPriority(&s2, cudaStreamNonBlocking, lo);
        cudaEventCreateWithFlags(&ev_fork, cudaEventDisableTiming);
        cudaEventCreateWithFlags(&ev_join, cudaEventDisableTiming);
    }

    prepX<<<NN * INF / 4 / 256, 256>>>(X);
    prepB<<<512, 256>>>(W, Wgc);

    // fork AFTER preps: GEMM and scan become schedulable at the same moment.
    // GEMM (high-pri stream 0, one wave) grabs its SM slots; the low-priority
    // scan fills the remaining thread slots -> DRAM/tensor overlap.
    cudaEventRecord(ev_fork, 0);
    cudaStreamWaitEvent(s2, ev_fork, 0);

    kernelGEMM<<<dim3(128, 2), 256>>>(a);
    kernelScan<<<NN, 256, 0, s2>>>(adj);

    cudaEventRecord(ev_join, s2);
    cudaStreamWaitEvent(0, ev_join, 0);

    kernelB<<<NN, 256>>>(bgc, out);
}

// round 16
// speedup vs baseline: 1.4760x; 1.0913x over previous
#include <cuda_runtime.h>
#include <cuda_fp16.h>
#include <cuda_bf16.h>
#include <cstdint>

#define NN    8192
#define INF   512
#define OUTF  256
#define MAXNB 1024

// ---------------- scratch (__device__ globals: allocation-free rule) --------
__device__ float          g_fs[NN];
__device__ float          g_fd[NN];
// pack layout per row: 64 groups x 16B; group g = {h[4g..4g+3], hgc[4g..4g+3]}
__device__ __half         g_pack[NN * 512];
__device__ int            g_ncnt[NN];
__device__ int            g_nidx[NN * MAXNB]; // pre-scaled j*512 (half units)
__device__ __nv_bfloat16  g_bh[INF * 512];  // [k][512] = W | Wgc (hi)
__device__ __nv_bfloat16  g_bl[INF * 512];  // lo

// ---------------- helpers ---------------------------------------------------
__device__ __forceinline__ uint32_t smem_u32(const void* p) {
    uint32_t a;
    asm("{ .reg .u64 t; cvta.to.shared.u64 t, %1; cvt.u32.u64 %0, t; }"
        : "=r"(a) : "l"(p));
    return a;
}
#define CPASYNC16(dst, src) \
    asm volatile("cp.async.cg.shared.global [%0], [%1], 16;" \
                 :: "r"(dst), "l"(src) : "memory")
#define CPCOMMIT() asm volatile("cp.async.commit_group;" ::: "memory")
#define CPWAIT(n)  asm volatile("cp.async.wait_group %0;" :: "n"(n) : "memory")

__device__ __forceinline__ void ldsm_x4(uint32_t (&r)[4], uint32_t addr) {
    asm volatile("ldmatrix.sync.aligned.m8n8.x4.shared.b16 {%0,%1,%2,%3}, [%4];"
                 : "=r"(r[0]), "=r"(r[1]), "=r"(r[2]), "=r"(r[3]) : "r"(addr));
}
__device__ __forceinline__ void ldsm_x4t(uint32_t (&r)[4], uint32_t addr) {
    asm volatile("ldmatrix.sync.aligned.m8n8.x4.trans.shared.b16 {%0,%1,%2,%3}, [%4];"
                 : "=r"(r[0]), "=r"(r[1]), "=r"(r[2]), "=r"(r[3]) : "r"(addr));
}
__device__ __forceinline__ void mma_bf16(float* c, const uint32_t* a,
                                         uint32_t b0, uint32_t b1) {
    asm volatile("mma.sync.aligned.m16n8k16.row.col.f32.bf16.bf16.f32 "
                 "{%0,%1,%2,%3}, {%4,%5,%6,%7}, {%8,%9}, {%0,%1,%2,%3};"
                 : "+f"(c[0]), "+f"(c[1]), "+f"(c[2]), "+f"(c[3])
                 : "r"(a[0]), "r"(a[1]), "r"(a[2]), "r"(a[3]), "r"(b0), "r"(b1));
}
__device__ __forceinline__ uint32_t pack_bf2(__nv_bfloat16 a, __nv_bfloat16 b) {
    __nv_bfloat162 t;
    t.x = a; t.y = b;
    return *(uint32_t*)&t;
}

// ---------------------------------------------------------------------------
// prepB: W,Wgc [512][256] fp32 -> g_bh/g_bl [512][512] bf16
// ---------------------------------------------------------------------------
__global__ __launch_bounds__(256) void prepB(const float* __restrict__ W,
                                             const float* __restrict__ Wgc) {
    int k = blockIdx.x, n = threadIdx.x;
    float w = W[k * 256 + n];
    __nv_bfloat16 hb = __float2bfloat16_rn(w);
    g_bh[k * 512 + n] = hb;
    g_bl[k * 512 + n] = __float2bfloat16_rn(w - __bfloat162float(hb));
    float wg = Wgc[k * 256 + n];
    hb = __float2bfloat16_rn(wg);
    g_bh[k * 512 + 256 + n] = hb;
    g_bl[k * 512 + 256 + n] = __float2bfloat16_rn(wg - __bfloat162float(hb));
}

// ---------------------------------------------------------------------------
// kernelScan: streaming adjacency scan (measured 47us @73% DRAM) - unchanged
// ---------------------------------------------------------------------------
__global__ __launch_bounds__(256, 8) void kernelScan(const float* __restrict__ adj) {
    __shared__ int s_cnt;
    const int row = blockIdx.x;
    const int tid = threadIdx.x;
    const int lane = tid & 31;
    if (tid == 0) s_cnt = 0;
    __syncthreads();

    const float4* arow = (const float4*)(adj + (size_t)row * NN);
    int* dst = g_nidx + row * MAXNB;

    #pragma unroll
    for (int half = 0; half < 2; half++) {
        float4 v[4];
        #pragma unroll
        for (int r = 0; r < 4; r++) v[r] = arow[tid + 256 * (half * 4 + r)];
        #pragma unroll
        for (int r = 0; r < 4; r++) {
            int q = tid + 256 * (half * 4 + r);
            float comp[4] = {v[r].x, v[r].y, v[r].z, v[r].w};
            #pragma unroll
            for (int ci = 0; ci < 4; ci++) {
                bool hit = comp[ci] > 0.f;
                unsigned m = __ballot_sync(0xFFFFFFFFu, hit);
                if (m) {
                    int base;
                    if (lane == 0) base = atomicAdd(&s_cnt, __popc(m));
                    base = __shfl_sync(0xFFFFFFFFu, base, 0);
                    if (hit) {
                        int pos = base + __popc(m & ((1u << lane) - 1u));
                        if (pos < MAXNB) dst[pos] = (q * 4 + ci) * 512;
                    }
                }
            }
        }
    }
    __syncthreads();
    if (tid == 0) g_ncnt[row] = min(s_cnt, MAXNB);
}

// ---------------------------------------------------------------------------
// kernelGEMM v2 (fixed): ONE pass over true K=512 (32 chunks of K=16).
// Per chunk: load X fp32 (convert to hi/lo bf16 in-kernel) + Bh + Bl, issue
// the 3 split terms back-to-back. A stride 48B (16B-aligned for ldmatrix).
// Epilogue f-staging overlays sm_ab (dead after mainloop) to fit 48KB smem.
// ---------------------------------------------------------------------------
#define ASTRIDE 48
#define ALO     3072                     // lo region offset (64 rows x 48B)
#define ABYTES  6144
#define BSTRIDE 528
#define BMAT    (16 * BSTRIDE)           // 8448 per B matrix (16 k-rows)
#define BUFB    (ABYTES + 2 * BMAT)      // 23040
__global__ __launch_bounds__(256, 2) void kernelGEMM(const float* __restrict__ X,
                                                     const float* __restrict__ avec) {
    __shared__ __align__(16) char sm_ab[2 * BUFB];
    __shared__ float s_avec[512];

    const int bm = blockIdx.x, bn = blockIdx.y;      // bn: 0=h, 1=hgc
    const int m0 = bm * 64;
    const int tid = threadIdx.x;
    const int wid = tid >> 5, lane = tid & 31;
    const int wm = wid & 1, wn = wid >> 1;           // warp tile 32m x 64n
    const uint32_t smbase = smem_u32(sm_ab);

    s_avec[tid] = avec[tid];
    s_avec[tid + 256] = avec[tid + 256];

    float cacc[2][8][4];
    #pragma unroll
    for (int i = 0; i < 2; i++)
        #pragma unroll
        for (int j = 0; j < 8; j++)
            #pragma unroll
            for (int e = 0; e < 4; e++) cacc[i][j][e] = 0.f;

    // A loader geometry: thread -> (row ar, float4 aq) of the 64x16 fp32 tile
    const int ar = tid >> 2, aq = tid & 3;
    const float4* xrow = (const float4*)(X + (size_t)(m0 + ar) * INF);

    auto issueB = [&](int c, uint32_t buf) {
        int kq = c * 16;
        const uint4* bh4 = (const uint4*)g_bh;
        const uint4* bl4 = (const uint4*)g_bl;
        #pragma unroll
        for (int i = 0; i < 2; i++) {
            int idx = tid + 256 * i;
            int rr = idx >> 5, q = idx & 31;
            CPASYNC16(buf + ABYTES + rr * BSTRIDE + q * 16,
                      bh4 + (size_t)(kq + rr) * 64 + bn * 32 + q);
            CPASYNC16(buf + ABYTES + BMAT + rr * BSTRIDE + q * 16,
                      bl4 + (size_t)(kq + rr) * 64 + bn * 32 + q);
        }
    };
    auto stsA = [&](const float4& v, uint32_t buf) {
        __nv_bfloat16 h[4], l[4];
        float f[4] = {v.x, v.y, v.z, v.w};
        #pragma unroll
        for (int i = 0; i < 4; i++) {
            h[i] = __float2bfloat16_rn(f[i]);
            l[i] = __float2bfloat16_rn(f[i] - __bfloat162float(h[i]));
        }
        uint32_t base = buf + ar * ASTRIDE + aq * 8;
        asm volatile("st.shared.v2.b32 [%0], {%1,%2};"
                     :: "r"(base), "r"(pack_bf2(h[0], h[1])), "r"(pack_bf2(h[2], h[3])) : "memory");
        asm volatile("st.shared.v2.b32 [%0], {%1,%2};"
                     :: "r"(base + ALO), "r"(pack_bf2(l[0], l[1])), "r"(pack_bf2(l[2], l[3])) : "memory");
    };

    // prologue
    float4 vA = xrow[aq];
    issueB(0, smbase); CPCOMMIT();
    stsA(vA, smbase);

    for (int c = 0; c < 32; c++) {
        uint32_t buf = smbase + (uint32_t)(c & 1) * BUFB;
        uint32_t nbuf = smbase + (uint32_t)((c + 1) & 1) * BUFB;
        if (c + 1 < 32) {
            vA = xrow[(c + 1) * 4 + aq];
            issueB(c + 1, nbuf); CPCOMMIT();
            CPWAIT(1);
        } else {
            CPWAIT(0);
        }
        __syncthreads();
        if (c + 1 < 32) stsA(vA, nbuf);

        // compute chunk c from buf
        uint32_t Ab = buf, Bb = buf + ABYTES;
        uint32_t ah[2][4], al[2][4], b[4][4];
        #pragma unroll
        for (int mf = 0; mf < 2; mf++) {
            uint32_t aaddr = Ab + (uint32_t)((wm * 32 + mf * 16 + (lane & 15)) * ASTRIDE
                                             + (lane >> 4) * 16);
            ldsm_x4(ah[mf], aaddr);
            ldsm_x4(al[mf], aaddr + ALO);
        }
        #pragma unroll
        for (int ng = 0; ng < 4; ng++)
            ldsm_x4t(b[ng], Bb + (uint32_t)((lane & 15) * BSTRIDE
                                            + (wn * 64 + ng * 16 + (lane >> 4) * 8) * 2));
        #pragma unroll
        for (int mf = 0; mf < 2; mf++)
            #pragma unroll
            for (int nf = 0; nf < 8; nf++)
                mma_bf16(cacc[mf][nf], ah[mf],
                         b[nf >> 1][(nf & 1) * 2], b[nf >> 1][(nf & 1) * 2 + 1]);
        #pragma unroll
        for (int mf = 0; mf < 2; mf++)
            #pragma unroll
            for (int nf = 0; nf < 8; nf++)
                mma_bf16(cacc[mf][nf], al[mf],
                         b[nf >> 1][(nf & 1) * 2], b[nf >> 1][(nf & 1) * 2 + 1]);
        #pragma unroll
        for (int ng = 0; ng < 4; ng++)
            ldsm_x4t(b[ng], Bb + BMAT + (uint32_t)((lane & 15) * BSTRIDE
                                            + (wn * 64 + ng * 16 + (lane >> 4) * 8) * 2));
        #pragma unroll
        for (int mf = 0; mf < 2; mf++)
            #pragma unroll
            for (int nf = 0; nf < 8; nf++)
                mma_bf16(cacc[mf][nf], ah[mf],
                         b[nf >> 1][(nf & 1) * 2], b[nf >> 1][(nf & 1) * 2 + 1]);
        __syncthreads();
    }

    // -------- epilogue: interleaved fp16 pack + complete f (bn==0) ----------
    // f-partial staging overlays sm_ab (mainloop data dead; synced above)
    float* s_fs = (float*)sm_ab;          // [4][64]
    float* s_fd = (float*)(sm_ab + 1024); // [4][64]
    const uint32_t gsub = (bn == 0) ? 0u : 8u;       // byte offset within group
    #pragma unroll
    for (int mf = 0; mf < 2; mf++) {
        #pragma unroll
        for (int half = 0; half < 2; half++) {
            int rl = wm * 32 + mf * 16 + (lane >> 2) + half * 8;   // local row
            float s1 = 0.f, s2 = 0.f;
            char* rowp = (char*)g_pack + (size_t)(m0 + rl) * 1024;
            #pragma unroll
            for (int nf = 0; nf < 8; nf++) {
                float v0 = cacc[mf][nf][half * 2 + 0];
                float v1 = cacc[mf][nf][half * 2 + 1];
                int c = wn * 64 + nf * 8 + 2 * (lane & 3);
                if (bn == 0) {
                    s1 += v0 * s_avec[c] + v1 * s_avec[c + 1];
                    s2 += v0 * s_avec[256 + c] + v1 * s_avec[256 + c + 1];
                }
                *(__half2*)(rowp + (c >> 2) * 16 + gsub + (c & 3) * 2) =
                    __floats2half2_rn(v0, v1);
            }
            if (bn == 0) {
                s1 += __shfl_xor_sync(0xFFFFFFFFu, s1, 1);
                s1 += __shfl_xor_sync(0xFFFFFFFFu, s1, 2);
                s2 += __shfl_xor_sync(0xFFFFFFFFu, s2, 1);
                s2 += __shfl_xor_sync(0xFFFFFFFFu, s2, 2);
                if ((lane & 3) == 0) {
                    s_fs[wn * 64 + rl] = s1;
                    s_fd[wn * 64 + rl] = s2;
                }
            }
        }
    }
    if (bn == 0) {
        __syncthreads();
        if (tid < 64) {
            g_fs[m0 + tid] = s_fs[0 * 64 + tid] + s_fs[1 * 64 + tid] +
                             s_fs[2 * 64 + tid] + s_fs[3 * 64 + tid];
            g_fd[m0 + tid] = s_fd[0 * 64 + tid] + s_fd[1 * 64 + tid] +
                             s_fd[2 * 64 + tid] + s_fd[3 * 64 + tid];
        }
    }
}

// ---------------------------------------------------------------------------
// kernelB: masked softmax + fused gather. 4-way neighbor split x 64 threads,
// ONE uint4 per (neighbor, thread) via the interleaved pack layout.
// ---------------------------------------------------------------------------
__global__ __launch_bounds__(256) void kernelB(const float* __restrict__ bgc,
                                               float* __restrict__ out) {
    __shared__ int    s_idx[MAXNB];
    __shared__ float  s_e[MAXNB];
    __shared__ float  s_red[256];
    __shared__ float4 s_att[256];
    __shared__ float4 s_gc[256];

    const int row = blockIdx.x;
    const int tid = threadIdx.x;
    const int cnt = g_ncnt[row];

    if (cnt > 0) {
        const float fsi = g_fs[row];
        float lm = -3e38f;
        for (int k = tid; k < cnt; k += 256) {
            int joff = g_nidx[row * MAXNB + k];      // j*512
            float e = fsi + g_fd[joff >> 9];
            e = (e > 0.f) ? e : 0.2f * e;
            s_idx[k] = joff;
            s_e[k] = e;
            lm = fmaxf(lm, e);
        }
        s_red[tid] = lm;
        __syncthreads();
        #pragma unroll
        for (int o = 128; o; o >>= 1) {
            if (tid < o) s_red[tid] = fmaxf(s_red[tid], s_red[tid + o]);
            __syncthreads();
        }
        const float mx = s_red[0];
        __syncthreads();

        float ls = 0.f;
        for (int k = tid; k < cnt; k += 256) {
            float w = expf(s_e[k] - mx);
            s_e[k] = w;
            ls += w;
        }
        s_red[tid] = ls;
        __syncthreads();
        #pragma unroll
        for (int o = 128; o; o >>= 1) {
            if (tid < o) s_red[tid] += s_red[tid + o];
            __syncthreads();
        }
        const float inv = 1.0f / s_red[0];
        __syncthreads();

        // gather: qg = neighbor subset (k % 4), tc = 4-col group; 1 uint4 each
        const int qg = tid >> 6, tc = tid & 63;
        float aa0 = 0.f, aa1 = 0.f, aa2 = 0.f, aa3 = 0.f;
        float gg0 = 0.f, gg1 = 0.f, gg2 = 0.f, gg3 = 0.f;
        const __half* hp = (const __half*)g_pack;
        #pragma unroll 4
        for (int k = qg; k < cnt; k += 4) {
            float w = s_e[k];
            uint4 pv = *(const uint4*)(hp + s_idx[k] + 8 * tc);
            float2 h01 = __half22float2(*(const __half2*)&pv.x);
            float2 h23 = __half22float2(*(const __half2*)&pv.y);
            float2 g01 = __half22float2(*(const __half2*)&pv.z);
            float2 g23 = __half22float2(*(const __half2*)&pv.w);
            aa0 += w * h01.x; aa1 += w * h01.y;
            aa2 += w * h23.x; aa3 += w * h23.y;
            gg0 += g01.x; gg1 += g01.y; gg2 += g23.x; gg3 += g23.y;
        }
        s_att[tid] = make_float4(aa0, aa1, aa2, aa3);
        s_gc[tid]  = make_float4(gg0, gg1, gg2, gg3);
        __syncthreads();

        if (tid < 64) {
            float4 a0 = s_att[tid],       a1 = s_att[64 + tid],
                   a2 = s_att[128 + tid], a3 = s_att[192 + tid];
            float4 g0 = s_gc[tid],        g1 = s_gc[64 + tid],
                   g2 = s_gc[128 + tid],  g3 = s_gc[192 + tid];
            float4 b = *(const float4*)(bgc + 4 * tid);
            float4 o;
            o.x = b.x + inv * (a0.x + a1.x + a2.x + a3.x) + (g0.x + g1.x + g2.x + g3.x);
            o.y = b.y + inv * (a0.y + a1.y + a2.y + a3.y) + (g0.y + g1.y + g2.y + g3.y);
            o.z = b.z + inv * (a0.z + a1.z + a2.z + a3.z) + (g0.z + g1.z + g2.z + g3.z);
            o.w = b.w + inv * (a0.w + a1.w + a2.w + a3.w) + (g0.w + g1.w + g2.w + g3.w);
            *(float4*)(out + (size_t)row * OUTF + 4 * tid) = o;
        }
    } else {
        // all-masked row: softmax uniform 1/N over all cols; gc = bias only
        const __half* hp = (const __half*)g_pack;
        float acc = 0.f;
        int hidx = (tid >> 2) * 8 + (tid & 3);       // col tid in interleaved layout
        for (int j = 0; j < NN; j++)
            acc += __half2float(hp[(size_t)j * 512 + hidx]);
        out[(size_t)row * OUTF + tid] = bgc[tid] + acc * (1.0f / (float)NN);
    }
}

// ---------------------------------------------------------------------------
extern "C" void kernel_launch(void* const* d_in, const int* in_sizes, int n_in,
                              void* d_out, int out_size) {
    const float* X   = (const float*)d_in[0];  // [8192, 512]
    const float* adj = (const float*)d_in[1];  // [8192, 8192]
    const float* W   = (const float*)d_in[2];  // [512, 256]
    const float* a   = (const float*)d_in[3];  // [512, 1]
    const float* Wgc = (const float*)d_in[4];  // [512, 256]
    const float* bgc = (const float*)d_in[5];  // [256]
    float* out = (float*)d_out;                // [8192, 256]

    static cudaStream_t s2 = nullptr;
    static cudaEvent_t ev_fork = nullptr, ev_join = nullptr;
    if (s2 == nullptr) {
        int lo, hi;
        cudaDeviceGetStreamPriorityRange(&lo, &hi);  // lo = LOWEST priority value
        cudaStreamCreateWithPriority(&s2, cudaStreamNonBlocking, lo);
        cudaEventCreateWithFlags(&ev_fork, cudaEventDisableTiming);
        cudaEventCreateWithFlags(&ev_join, cudaEventDisableTiming);
    }

    prepB<<<512, 256>>>(W, Wgc);

    // fork: GEMM (default stream, one wave) + scan (low-pri stream) co-run
    cudaEventRecord(ev_fork, 0);
    cudaStreamWaitEvent(s2, ev_fork, 0);

    kernelGEMM<<<dim3(128, 2), 256>>>(X, a);
    kernelScan<<<NN, 256, 0, s2>>>(adj);

    cudaEventRecord(ev_join, s2);
    cudaStreamWaitEvent(0, ev_join, 0);

    kernelB<<<NN, 256>>>(bgc, out);
}